// round 12
// baseline (speedup 1.0000x reference)
#include <cuda_runtime.h>
#include <cstdint>

#define S0_N 663552
#define S1_N 73728
#define S2_N 8192
#define FEAT 128
#define CONT 256
#define FAN  8

typedef unsigned long long u64;

// ---------------- scratch (static device globals; no allocation) ------------
__device__ float g_h0[(size_t)S0_N * FEAT];   // ~324 MB
__device__ float g_h1[(size_t)S1_N * FEAT];   // ~36 MB
__device__ unsigned char g_flag[S0_N];
__device__ int g_list[S0_N];
__device__ int g_count;

// ---------------- helpers ---------------------------------------------------
__device__ __forceinline__ float leakyf(float x) { return x > 0.f ? x : 0.1f * x; }

__device__ __forceinline__ u64 packf2(float a, float b) {
    u64 r;
    asm("mov.b64 %0, {%1, %2};" : "=l"(r)
        : "r"(__float_as_uint(a)), "r"(__float_as_uint(b)));
    return r;
}
__device__ __forceinline__ void unpackf2(u64 v, float& a, float& b) {
    unsigned int u0, u1;
    asm("mov.b64 {%0, %1}, %2;" : "=r"(u0), "=r"(u1) : "l"(v));
    a = __uint_as_float(u0); b = __uint_as_float(u1);
}
__device__ __forceinline__ u64 fma2(u64 a, u64 b, u64 c) {
    u64 d;
    asm("fma.rn.f32x2 %0, %1, %2, %3;" : "=l"(d) : "l"(a), "l"(b), "l"(c));
    return d;
}

// ---------------- tiny setup kernels ----------------------------------------
__global__ void k_reset() {
    int t = blockIdx.x * blockDim.x + threadIdx.x;
    if (t < S0_N / 16) ((int4*)g_flag)[t] = make_int4(0, 0, 0, 0);
    if (t == 0) g_count = 0;
}

__global__ void k_mark(const int* __restrict__ src0) {
    int t = blockIdx.x * blockDim.x + threadIdx.x;   // grid covers 9*S1 exactly
    g_flag[src0[t]] = 1;
    if (t < S1_N) g_flag[t] = 1;
}

__global__ void k_compact() {
    int t = blockIdx.x * blockDim.x + threadIdx.x;   // grid covers S0 exactly
    int f = (g_flag[t] != 0);
    unsigned m = __ballot_sync(0xffffffffu, f);
    int lane = threadIdx.x & 31;
    int base = 0;
    if (lane == 0) base = atomicAdd(&g_count, __popc(m));
    base = __shfl_sync(0xffffffffu, base, 0);
    if (f) g_list[base + __popc(m & ((1u << lane) - 1u))] = t;
}

// ---------------- h0 = node_emb[parent+1] + leaky(content @ Wp^T + bp) ------
// 128 rows x 128 cols per block, 256 threads, 8 rows x 4 col-pairs per thread.
// Content in smem as duplicated pairs (a,a): LDS.128 covers 2 k-steps, feeds
// FFMA2 directly. Weights paired over ADJACENT output columns (2c,2c+1) with
// k-parity interleaved: one LDS.128 yields both k-steps' pairs; layout
// ws2[k2*132 + c2*2 + kb] is conflict-free for loads AND stores.
#define H0_SMEM_BYTES ((4352 + 2112) * 8 + 1024)

__global__ void __launch_bounds__(256, 2) k_h0(
    const float* __restrict__ content, const float* __restrict__ Wp,
    const float* __restrict__ bp, const float* __restrict__ node_emb,
    const int* __restrict__ parent)
{
    extern __shared__ u64 dyn[];
    u64* cs64  = dyn;                 // [128][34] dup pairs (32 k used)
    u64* ws2   = dyn + 4352;          // [16][132]: k2*132 + c2*2 + kb
    int* rid_s = (int*)(dyn + 6464);
    int* par_s = rid_s + 128;

    const int cnt = g_count;
    const int b0r = blockIdx.x * 128;
    if (b0r >= cnt) return;

    const int t = threadIdx.x;
    if (t < 128) {
        int g = b0r + t;
        int rid = g_list[(g < cnt) ? g : (cnt - 1)];
        rid_s[t] = rid;
        par_s[t] = parent[rid] + 1;
    }
    __syncthreads();

    const int ty = t >> 4, tx = t & 15;

    // content loader role: 1 thread = 1 row-half (16 contiguous floats)
    const int crow_i = t & 127, ckh = t >> 7;
    const float* cptr = content + (size_t)rid_s[crow_i] * CONT + ckh * 16;
    // weight loader role: 1 thread = column-pair (2*wc2, 2*wc2+1), 8 k-vals
    const int wc2 = t & 63, wkh = t >> 6;
    const float* wA = Wp + (size_t)(2 * wc2) * CONT + wkh * 8;
    const float* wB = wA + CONT;

    // prefetch chunk 0 content
    float4 pf[4];
#pragma unroll
    for (int j = 0; j < 4; j++) pf[j] = *(const float4*)(cptr + j * 4);

    u64 acc[8][4];
#pragma unroll
    for (int r = 0; r < 8; r++)
#pragma unroll
        for (int j = 0; j < 4; j++) acc[r][j] = 0ull;

    for (int c = 0; c < 8; c++) {
        const int kc = c * 32;
        // weight loads (L2-resident) before the barrier
        float4 va0 = *(const float4*)(wA + kc);
        float4 va1 = *(const float4*)(wA + kc + 4);
        float4 vb0 = *(const float4*)(wB + kc);
        float4 vb1 = *(const float4*)(wB + kc + 4);

        if (c) __syncthreads();

        // content dup stores (conflict-free STS.128: chunk = row&7 per phase)
        {
            u64* cd = cs64 + crow_i * 34 + ckh * 16;
#pragma unroll
            for (int j = 0; j < 4; j++) {
                float4 v = pf[j];
                *(ulonglong2*)(cd + j * 4) =
                    make_ulonglong2(packf2(v.x, v.x), packf2(v.y, v.y));
                *(ulonglong2*)(cd + j * 4 + 2) =
                    make_ulonglong2(packf2(v.z, v.z), packf2(v.w, v.w));
            }
        }
        // weight paired stores (conflict-free STS.128: chunk = c2&7)
        {
            u64* wd = ws2 + wc2 * 2;
            const float* a0 = (const float*)&va0;
            const float* a1 = (const float*)&va1;
            const float* b0 = (const float*)&vb0;
            const float* b1 = (const float*)&vb1;
#pragma unroll
            for (int e2 = 0; e2 < 2; e2++)
                *(ulonglong2*)(wd + (wkh * 4 + e2) * 132) =
                    make_ulonglong2(packf2(a0[2 * e2],     b0[2 * e2]),
                                    packf2(a0[2 * e2 + 1], b0[2 * e2 + 1]));
#pragma unroll
            for (int e2 = 0; e2 < 2; e2++)
                *(ulonglong2*)(wd + (wkh * 4 + 2 + e2) * 132) =
                    make_ulonglong2(packf2(a1[2 * e2],     b1[2 * e2]),
                                    packf2(a1[2 * e2 + 1], b1[2 * e2 + 1]));
        }
        __syncthreads();

        // prefetch next chunk content while computing
        if (c < 7) {
#pragma unroll
            for (int j = 0; j < 4; j++)
                pf[j] = *(const float4*)(cptr + kc + 32 + j * 4);
        }

        const u64* csr = cs64 + (ty * 8) * 34;
        const u64* wsb = ws2 + tx * 2;
#pragma unroll 4
        for (int kk = 0; kk < 32; kk += 2) {
            const u64* wrow = wsb + (kk >> 1) * 132;
            ulonglong2 w0 = *(const ulonglong2*)(wrow);
            ulonglong2 w1 = *(const ulonglong2*)(wrow + 32);
            ulonglong2 w2 = *(const ulonglong2*)(wrow + 64);
            ulonglong2 w3 = *(const ulonglong2*)(wrow + 96);
#pragma unroll
            for (int r = 0; r < 8; r++) {
                ulonglong2 ap = *(const ulonglong2*)(csr + r * 34 + kk);
                acc[r][0] = fma2(ap.x, w0.x, acc[r][0]);
                acc[r][1] = fma2(ap.x, w1.x, acc[r][1]);
                acc[r][2] = fma2(ap.x, w2.x, acc[r][2]);
                acc[r][3] = fma2(ap.x, w3.x, acc[r][3]);
                acc[r][0] = fma2(ap.y, w0.y, acc[r][0]);
                acc[r][1] = fma2(ap.y, w1.y, acc[r][1]);
                acc[r][2] = fma2(ap.y, w2.y, acc[r][2]);
                acc[r][3] = fma2(ap.y, w3.y, acc[r][3]);
            }
        }
    }

    // epilogue: acc[r][j] = output cols (2tx+32j, 2tx+32j+1)
    float2 bpv[4];
#pragma unroll
    for (int j = 0; j < 4; j++) bpv[j] = *(const float2*)(bp + 2 * tx + 32 * j);

#pragma unroll
    for (int r = 0; r < 8; r++) {
        int lr = ty * 8 + r;
        if (b0r + lr >= cnt) continue;
        const float* ne = node_emb + (size_t)par_s[lr] * FEAT;
        float* dst = g_h0 + (size_t)rid_s[lr] * FEAT;
#pragma unroll
        for (int j = 0; j < 4; j++) {
            float x0, x1;
            unpackf2(acc[r][j], x0, x1);
            int c0 = 2 * tx + 32 * j;
            float2 n = *(const float2*)(ne + c0);
            float2 o;
            o.x = leakyf(x0 + bpv[j].x) + n.x;
            o.y = leakyf(x1 + bpv[j].y) + n.y;
            *(float2*)(dst + c0) = o;
        }
    }
}

// ---------------- SAGE conv layer -------------------------------------------
// 64 dst rows x 128 cols per block. Per-chunk staging of X into duplicated
// pairs (Xd1 = h_dst cols, Xd2 = h_agg cols) + adjacent-column-paired weights,
// so the inner loop is pure LDS.128 -> FFMA2.
#define CONV_SMEM_BYTES ((3 * 1056 + 2 * 1152) * 8 + 64 * 260 * 4)

template <int LAST>
__global__ void __launch_bounds__(256, 2) k_conv(
    const float* __restrict__ hsrc, const float* __restrict__ hdst,
    const int* __restrict__ srcArr, int n_dst,
    const float* __restrict__ W, const float* __restrict__ bb,
    const float* __restrict__ Wagg, const float* __restrict__ bagg,
    float* __restrict__ out)
{
    extern __shared__ u64 dyn[];
    u64* Wa2 = dyn;                 // [8][132]
    u64* Wb2 = dyn + 1056;
    u64* Wg2 = dyn + 2112;
    u64* Xd1 = dyn + 3168;          // [64][18] dup pairs (16 k used)
    u64* Xd2 = dyn + 3168 + 1152;
    float* Xs = (float*)(dyn + 5472);   // [64][260]

    const int t = threadIdx.x;

    // ---- gather phase: 4 threads per row, 32 feats each ----
    {
        int row = t >> 2, q = t & 3, f0 = q * 32;
        size_t i = (size_t)blockIdx.x * 64 + row;
        const float* pd = hdst + i * FEAT + f0;
        const float* ps = hsrc + i * FEAT + f0;
        float4 hd[8], s[8];
#pragma unroll
        for (int j = 0; j < 8; j++) {
            hd[j] = *(const float4*)(pd + 4 * j);
            s[j]  = *(const float4*)(ps + 4 * j);   // self edge
        }
        int eb = n_dst + (int)i * FAN;
#pragma unroll
        for (int e = 0; e < FAN; e++) {
            const float* pe = hsrc + (size_t)srcArr[eb + e] * FEAT + f0;
#pragma unroll
            for (int j = 0; j < 8; j++) {
                float4 u = *(const float4*)(pe + 4 * j);
                s[j].x += u.x; s[j].y += u.y; s[j].z += u.z; s[j].w += u.w;
            }
        }
        float* xr = Xs + row * 260;
#pragma unroll
        for (int j = 0; j < 8; j++) {
            *(float4*)(xr + f0 + 4 * j) = hd[j];
            float4 ag;
            ag.x = (s[j].x - hd[j].x) * 0.125f;
            ag.y = (s[j].y - hd[j].y) * 0.125f;
            ag.z = (s[j].z - hd[j].z) * 0.125f;
            ag.w = (s[j].w - hd[j].w) * 0.125f;
            *(float4*)(xr + 128 + f0 + 4 * j) = ag;
        }
    }
    __syncthreads();

    const int ty = t >> 4, tx = t & 15;
    // weight loader role: column pair (2*wc2, 2*wc2+1), 4 k-vals per chunk
    const int wc2 = t & 63, wkh = t >> 6;
    const float* pWa = W    + (size_t)(2 * wc2) * 256 + wkh * 4;
    const float* pWb = pWa + 128;
    const float* pWg = Wagg + (size_t)(2 * wc2) * 128 + wkh * 4;
    // staging role: 1 thread = (row, mat, k-half)
    const int srow = t & 63, ssel = t >> 6;
    const int smat = ssel >> 1, skh = ssel & 1;
    u64* sxd = (smat ? Xd2 : Xd1) + srow * 18 + skh * 8;
    const float* sxs = Xs + srow * 260 + smat * 128 + skh * 8;

    u64 aN[4][4], aA[4][4];
#pragma unroll
    for (int r = 0; r < 4; r++)
#pragma unroll
        for (int j = 0; j < 4; j++) { aN[r][j] = 0ull; aA[r][j] = 0ull; }

    for (int kc = 0; kc < FEAT; kc += 16) {
        float4 va  = *(const float4*)(pWa + kc);
        float4 vaB = *(const float4*)(pWa + 256 + kc);
        float4 vb  = *(const float4*)(pWb + kc);
        float4 vbB = *(const float4*)(pWb + 256 + kc);
        float4 vg  = *(const float4*)(pWg + kc);
        float4 vgB = *(const float4*)(pWg + 128 + kc);
        float4 s0  = *(const float4*)(sxs + kc);        // Xs stable after gather
        float4 s1  = *(const float4*)(sxs + kc + 4);

        if (kc) __syncthreads();

        // stage X dup pairs (conflict-free STS.128: chunk = row&7)
        *(ulonglong2*)(sxd + 0) = make_ulonglong2(packf2(s0.x, s0.x), packf2(s0.y, s0.y));
        *(ulonglong2*)(sxd + 2) = make_ulonglong2(packf2(s0.z, s0.z), packf2(s0.w, s0.w));
        *(ulonglong2*)(sxd + 4) = make_ulonglong2(packf2(s1.x, s1.x), packf2(s1.y, s1.y));
        *(ulonglong2*)(sxd + 6) = make_ulonglong2(packf2(s1.z, s1.z), packf2(s1.w, s1.w));
        // paired weight stores
        {
            u64* wda = Wa2 + wc2 * 2;
            u64* wdb = Wb2 + wc2 * 2;
            u64* wdg = Wg2 + wc2 * 2;
            *(ulonglong2*)(wda + (wkh * 2) * 132) =
                make_ulonglong2(packf2(va.x, vaB.x), packf2(va.y, vaB.y));
            *(ulonglong2*)(wda + (wkh * 2 + 1) * 132) =
                make_ulonglong2(packf2(va.z, vaB.z), packf2(va.w, vaB.w));
            *(ulonglong2*)(wdb + (wkh * 2) * 132) =
                make_ulonglong2(packf2(vb.x, vbB.x), packf2(vb.y, vbB.y));
            *(ulonglong2*)(wdb + (wkh * 2 + 1) * 132) =
                make_ulonglong2(packf2(vb.z, vbB.z), packf2(vb.w, vbB.w));
            *(ulonglong2*)(wdg + (wkh * 2) * 132) =
                make_ulonglong2(packf2(vg.x, vgB.x), packf2(vg.y, vgB.y));
            *(ulonglong2*)(wdg + (wkh * 2 + 1) * 132) =
                make_ulonglong2(packf2(vg.z, vgB.z), packf2(vg.w, vgB.w));
        }
        __syncthreads();

        const u64* x1b = Xd1 + (ty * 4) * 18;
        const u64* x2b = Xd2 + (ty * 4) * 18;
#pragma unroll
        for (int kk = 0; kk < 16; kk += 2) {
            const int k2 = kk >> 1;
            ulonglong2 A1[4], A2[4];
#pragma unroll
            for (int ri = 0; ri < 4; ri++) {
                A1[ri] = *(const ulonglong2*)(x1b + ri * 18 + kk);
                A2[ri] = *(const ulonglong2*)(x2b + ri * 18 + kk);
            }
#pragma unroll
            for (int j = 0; j < 4; j++) {
                const int wo = k2 * 132 + (tx + 16 * j) * 2;
                ulonglong2 wa = *(const ulonglong2*)(Wa2 + wo);
                ulonglong2 wb = *(const ulonglong2*)(Wb2 + wo);
                ulonglong2 wg = *(const ulonglong2*)(Wg2 + wo);
#pragma unroll
                for (int ri = 0; ri < 4; ri++) {
                    aN[ri][j] = fma2(A1[ri].x, wa.x, aN[ri][j]);
                    aN[ri][j] = fma2(A2[ri].x, wb.x, aN[ri][j]);
                    aA[ri][j] = fma2(A2[ri].x, wg.x, aA[ri][j]);
                    aN[ri][j] = fma2(A1[ri].y, wa.y, aN[ri][j]);
                    aN[ri][j] = fma2(A2[ri].y, wb.y, aN[ri][j]);
                    aA[ri][j] = fma2(A2[ri].y, wg.y, aA[ri][j]);
                }
            }
        }
    }

    // ---- epilogue: cols (2tx+32j, 2tx+32j+1) ----
    float2 bv[4], bgv[4];
#pragma unroll
    for (int j = 0; j < 4; j++) {
        bv[j]  = *(const float2*)(bb   + 2 * tx + 32 * j);
        bgv[j] = *(const float2*)(bagg + 2 * tx + 32 * j);
    }

#pragma unroll
    for (int ri = 0; ri < 4; ri++) {
        size_t irow = (size_t)blockIdx.x * 64 + ty * 4 + ri;
        float h[4][2];
#pragma unroll
        for (int j = 0; j < 4; j++) {
            float n0, n1, a0, a1;
            unpackf2(aN[ri][j], n0, n1);
            unpackf2(aA[ri][j], a0, a1);
            float hn0 = n0 + bv[j].x,  hn1 = n1 + bv[j].y;
            float ha0 = a0 + bgv[j].x, ha1 = a1 + bgv[j].y;
            if (!LAST) { hn0 = leakyf(hn0); hn1 = leakyf(hn1);
                         ha0 = leakyf(ha0); ha1 = leakyf(ha1); }
            h[j][0] = hn0 + ha0; h[j][1] = hn1 + ha1;
        }
        if (!LAST) {
            float ss = 0.f;
#pragma unroll
            for (int j = 0; j < 4; j++) ss += h[j][0] * h[j][0] + h[j][1] * h[j][1];
            ss += __shfl_xor_sync(0xffffffffu, ss, 1);
            ss += __shfl_xor_sync(0xffffffffu, ss, 2);
            ss += __shfl_xor_sync(0xffffffffu, ss, 4);
            ss += __shfl_xor_sync(0xffffffffu, ss, 8);
            float inv = 1.0f / fmaxf(sqrtf(ss), 1e-6f);
#pragma unroll
            for (int j = 0; j < 4; j++) { h[j][0] *= inv; h[j][1] *= inv; }
        }
        float* po = out + irow * FEAT;
#pragma unroll
        for (int j = 0; j < 4; j++) {
            float2 o; o.x = h[j][0]; o.y = h[j][1];
            *(float2*)(po + 2 * tx + 32 * j) = o;
        }
    }
}

// ---------------- launch -----------------------------------------------------
extern "C" void kernel_launch(void* const* d_in, const int* in_sizes, int n_in,
                              void* d_out, int out_size)
{
    const float* node_emb = (const float*)d_in[0];
    const float* content0 = (const float*)d_in[1];
    const float* Wp       = (const float*)d_in[2];
    const float* bp       = (const float*)d_in[3];
    const float* W0       = (const float*)d_in[4];
    const float* b0       = (const float*)d_in[5];
    const float* Wagg0    = (const float*)d_in[6];
    const float* bagg0    = (const float*)d_in[7];
    const float* W1       = (const float*)d_in[8];
    const float* b1       = (const float*)d_in[9];
    const float* Wagg1    = (const float*)d_in[10];
    const float* bagg1    = (const float*)d_in[11];
    const int*   parent0  = (const int*)d_in[12];
    const int*   src0     = (const int*)d_in[13];
    const int*   src1     = (const int*)d_in[15];
    float* out = (float*)d_out;

    (void)in_sizes; (void)n_in; (void)out_size;

    cudaFuncSetAttribute(k_h0, cudaFuncAttributeMaxDynamicSharedMemorySize, H0_SMEM_BYTES);
    cudaFuncSetAttribute(k_conv<0>, cudaFuncAttributeMaxDynamicSharedMemorySize, CONV_SMEM_BYTES);
    cudaFuncSetAttribute(k_conv<1>, cudaFuncAttributeMaxDynamicSharedMemorySize, CONV_SMEM_BYTES);

    void *p0, *p1;
    cudaGetSymbolAddress(&p0, g_h0);
    cudaGetSymbolAddress(&p1, g_h1);
    float* h0p = (float*)p0;
    float* h1p = (float*)p1;

    k_reset  <<<(S0_N / 16 + 255) / 256, 256>>>();
    k_mark   <<<(9 * S1_N) / 256, 256>>>(src0);
    k_compact<<<S0_N / 256, 256>>>();
    k_h0     <<<S0_N / 128, 256, H0_SMEM_BYTES>>>(content0, Wp, bp, node_emb, parent0);
    k_conv<0><<<S1_N / 64, 256, CONV_SMEM_BYTES>>>(h0p, h0p, src0, S1_N,
                                                   W0, b0, Wagg0, bagg0, h1p);
    k_conv<1><<<S2_N / 64, 256, CONV_SMEM_BYTES>>>(h1p, h0p, src1, S2_N,
                                                   W1, b1, Wagg1, bagg1, out);
}

// round 16
// speedup vs baseline: 1.7387x; 1.7387x over previous
#include <cuda_runtime.h>
#include <cstdint>

#define S0_N 663552
#define S1_N 73728
#define S2_N 8192
#define FEAT 128
#define CONT 256
#define FAN  8

typedef unsigned long long u64;

// ---------------- scratch (static device globals; no allocation) ------------
__device__ float g_h0[(size_t)S0_N * FEAT];   // ~324 MB
__device__ float g_h1[(size_t)S1_N * FEAT];   // ~36 MB
__device__ unsigned char g_flag[S0_N];
__device__ int g_list[S0_N];
__device__ int g_count;

// ---------------- helpers ---------------------------------------------------
__device__ __forceinline__ float leakyf(float x) { return x > 0.f ? x : 0.1f * x; }

__device__ __forceinline__ u64 packf2(float a, float b) {
    u64 r;
    asm("mov.b64 %0, {%1, %2};" : "=l"(r)
        : "r"(__float_as_uint(a)), "r"(__float_as_uint(b)));
    return r;
}
__device__ __forceinline__ void unpackf2(u64 v, float& a, float& b) {
    unsigned int u0, u1;
    asm("mov.b64 {%0, %1}, %2;" : "=r"(u0), "=r"(u1) : "l"(v));
    a = __uint_as_float(u0); b = __uint_as_float(u1);
}
__device__ __forceinline__ u64 fma2(u64 a, u64 b, u64 c) {
    u64 d;
    asm("fma.rn.f32x2 %0, %1, %2, %3;" : "=l"(d) : "l"(a), "l"(b), "l"(c));
    return d;
}

__device__ __forceinline__ uint32_t s2u(const void* p) {
    uint32_t a;
    asm("{ .reg .u64 t; cvta.to.shared.u64 t, %1; cvt.u32.u64 %0, t; }"
        : "=r"(a) : "l"(p));
    return a;
}

// SW128 swizzle (XOR 16B-column with row&7)
#define SWZ(o) ((o) ^ (((o) >> 3) & 0x70))

// split fp32 pair -> bf16x2 hi + bf16x2 lo (f0 in low half)
__device__ __forceinline__ void split2(float f0, float f1,
                                       uint32_t& hi, uint32_t& lo) {
    asm("cvt.rn.bf16x2.f32 %0, %1, %2;" : "=r"(hi) : "f"(f1), "f"(f0));
    float r0 = f0 - __uint_as_float(hi << 16);
    float r1 = f1 - __uint_as_float(hi & 0xffff0000u);
    asm("cvt.rn.bf16x2.f32 %0, %1, %2;" : "=r"(lo) : "f"(r1), "f"(r0));
}

// ldmatrix x4 (sm_75+ baseline feature)
__device__ __forceinline__ void ldsm4(uint32_t* r, uint32_t addr) {
    asm volatile("ldmatrix.sync.aligned.m8n8.x4.shared.b16 {%0,%1,%2,%3}, [%4];"
        : "=r"(r[0]), "=r"(r[1]), "=r"(r[2]), "=r"(r[3]) : "r"(addr));
}

// mma.sync m16n8k16 bf16 (sm_80+ baseline feature)
__device__ __forceinline__ void mma16816(float* d, const uint32_t* a,
                                         uint32_t b0, uint32_t b1) {
    asm volatile("mma.sync.aligned.m16n8k16.row.col.f32.bf16.bf16.f32 "
        "{%0,%1,%2,%3},{%4,%5,%6,%7},{%8,%9},{%0,%1,%2,%3};"
        : "+f"(d[0]), "+f"(d[1]), "+f"(d[2]), "+f"(d[3])
        : "r"(a[0]), "r"(a[1]), "r"(a[2]), "r"(a[3]), "r"(b0), "r"(b1));
}

// ---------------- tiny setup kernels ----------------------------------------
__global__ void k_reset() {
    int t = blockIdx.x * blockDim.x + threadIdx.x;
    if (t < S0_N / 16) ((int4*)g_flag)[t] = make_int4(0, 0, 0, 0);
    if (t == 0) g_count = 0;
}

__global__ void k_mark(const int* __restrict__ src0) {
    int t = blockIdx.x * blockDim.x + threadIdx.x;   // grid covers 9*S1 exactly
    g_flag[src0[t]] = 1;
    if (t < S1_N) g_flag[t] = 1;
}

__global__ void k_compact() {
    int t = blockIdx.x * blockDim.x + threadIdx.x;   // grid covers S0 exactly
    int f = (g_flag[t] != 0);
    unsigned m = __ballot_sync(0xffffffffu, f);
    int lane = threadIdx.x & 31;
    int base = 0;
    if (lane == 0) base = atomicAdd(&g_count, __popc(m));
    base = __shfl_sync(0xffffffffu, base, 0);
    if (f) g_list[base + __popc(m & ((1u << lane) - 1u))] = t;
}

// ---------------- h0 via mma.sync bf16-split GEMM ---------------------------
// Per CTA: 128 gathered rows x 128 cols, K=256 in 4 chunks of 64.
// smem: SW128-swizzled bf16 planes A_hi/A_lo (content) and B_hi/B_lo (Wp).
// 8 warps in 4x2 tile grid, warp tile 32x64; 3 products hh+hl+lh per frag.
#define P_AH 0
#define P_AL 16384
#define P_BH 32768
#define P_BL 49152
#define RID_OFF 65536
#define PAR_OFF 66048
#define H0_SMEM_BYTES 66560

__global__ void __launch_bounds__(256, 2) k_h0(
    const float* __restrict__ content, const float* __restrict__ Wp,
    const float* __restrict__ bp, const float* __restrict__ node_emb,
    const int* __restrict__ parent)
{
    extern __shared__ char smem[];
    const int cnt = g_count;
    const int b0r = blockIdx.x * 128;
    if (b0r >= cnt) return;

    const uint32_t sb = s2u(smem);
    const int t = threadIdx.x;
    const int wid = t >> 5, lid = t & 31;

    int* rid_s = (int*)(smem + RID_OFF);
    int* par_s = (int*)(smem + PAR_OFF);
    if (t < 128) {
        int g = b0r + t;
        int rid = g_list[(g < cnt) ? g : (cnt - 1)];
        rid_s[t] = rid;
        par_s[t] = parent[rid] + 1;
    }
    __syncthreads();

    // loader role: thread = (row, half); 32 fp32 per chunk each
    const int row = t >> 1, half = t & 1;
    const float* aP = content + (size_t)rid_s[row] * CONT + half * 32;
    const float* bP = Wp + (size_t)row * CONT + half * 32;
    const uint32_t rbase = (uint32_t)(row * 128 + half * 64);

    // mma roles
    const int wr = wid & 3, wc = wid >> 2;
    const int arow0 = wr * 32 + (lid & 15);
    const int brow0 = wc * 64 + (lid & 15);
    const int csel  = (lid >> 4) * 16;

    float acc[2][8][4];
#pragma unroll
    for (int mb = 0; mb < 2; mb++)
#pragma unroll
        for (int nb = 0; nb < 8; nb++)
#pragma unroll
            for (int q = 0; q < 4; q++) acc[mb][nb][q] = 0.f;

    for (int c = 0; c < 4; c++) {
        // ---- load + split A and B chunk (64 fp32 per row; this thread: 32) ----
        float av[32], bv[32];
#pragma unroll
        for (int q = 0; q < 8; q++) {
            *(float4*)(av + 4 * q) = *(const float4*)(aP + 64 * c + 4 * q);
            *(float4*)(bv + 4 * q) = *(const float4*)(bP + 64 * c + 4 * q);
        }
        uint32_t ahi[16], alo[16], bhi[16], blo[16];
#pragma unroll
        for (int i = 0; i < 16; i++) {
            split2(av[2 * i], av[2 * i + 1], ahi[i], alo[i]);
            split2(bv[2 * i], bv[2 * i + 1], bhi[i], blo[i]);
        }

        if (c) __syncthreads();   // previous chunk's mma reads done

#pragma unroll
        for (int q = 0; q < 4; q++) {
            uint32_t so = SWZ(rbase + q * 16);
            *(uint4*)(smem + P_AH + so) = *(uint4*)(ahi + 4 * q);
            *(uint4*)(smem + P_AL + so) = *(uint4*)(alo + 4 * q);
            *(uint4*)(smem + P_BH + so) = *(uint4*)(bhi + 4 * q);
            *(uint4*)(smem + P_BL + so) = *(uint4*)(blo + 4 * q);
        }
        __syncthreads();

        // ---- mma over 4 k16 steps ----
#pragma unroll
        for (int ks = 0; ks < 4; ks++) {
            const int kb = ks * 32;
            uint32_t Ah[2][4], Al[2][4];
            ldsm4(Ah[0], sb + P_AH + SWZ(arow0 * 128 + csel + kb));
            ldsm4(Ah[1], sb + P_AH + SWZ((arow0 + 16) * 128 + csel + kb));
            ldsm4(Al[0], sb + P_AL + SWZ(arow0 * 128 + csel + kb));
            ldsm4(Al[1], sb + P_AL + SWZ((arow0 + 16) * 128 + csel + kb));
#pragma unroll
            for (int nb = 0; nb < 4; nb++) {
                uint32_t Bh[4], Bl[4];
                ldsm4(Bh, sb + P_BH + SWZ((brow0 + nb * 16) * 128 + csel + kb));
                ldsm4(Bl, sb + P_BL + SWZ((brow0 + nb * 16) * 128 + csel + kb));
#pragma unroll
                for (int mb = 0; mb < 2; mb++) {
                    float* d0 = acc[mb][nb * 2];
                    float* d1 = acc[mb][nb * 2 + 1];
                    mma16816(d0, Ah[mb], Bh[0], Bh[2]);
                    mma16816(d0, Ah[mb], Bl[0], Bl[2]);
                    mma16816(d0, Al[mb], Bh[0], Bh[2]);
                    mma16816(d1, Ah[mb], Bh[1], Bh[3]);
                    mma16816(d1, Ah[mb], Bl[1], Bl[3]);
                    mma16816(d1, Al[mb], Bh[1], Bh[3]);
                }
            }
        }
    }

    // ---- epilogue: c-frag rows wr*32+mb*16+rh*8+lid/4, cols wc*64+nb*8+2*(lid%4)
    const int l4 = lid >> 2, lp = lid & 3;
#pragma unroll
    for (int mb = 0; mb < 2; mb++) {
#pragma unroll
        for (int rh = 0; rh < 2; rh++) {
            int lrow = wr * 32 + mb * 16 + rh * 8 + l4;
            if (b0r + lrow >= cnt) continue;
            const float* ne = node_emb + (size_t)par_s[lrow] * FEAT;
            float* dst = g_h0 + (size_t)rid_s[lrow] * FEAT;
#pragma unroll
            for (int nb = 0; nb < 8; nb++) {
                int col = wc * 64 + nb * 8 + 2 * lp;
                float v0 = acc[mb][nb][rh * 2 + 0];
                float v1 = acc[mb][nb][rh * 2 + 1];
                float2 nn = *(const float2*)(ne + col);
                float2 o;
                o.x = leakyf(v0 + __ldg(bp + col))     + nn.x;
                o.y = leakyf(v1 + __ldg(bp + col + 1)) + nn.y;
                *(float2*)(dst + col) = o;
            }
        }
    }
}

// ---------------- SAGE conv layer (round-9 best config) ---------------------
#define CONV_SMEM_BYTES (64 * 260 * 4 + 3 * 16 * 68 * 8)

template <int LAST>
__global__ void __launch_bounds__(256, 2) k_conv(
    const float* __restrict__ hsrc, const float* __restrict__ hdst,
    const int* __restrict__ srcArr, int n_dst,
    const float* __restrict__ W, const float* __restrict__ bb,
    const float* __restrict__ Wagg, const float* __restrict__ bagg,
    float* __restrict__ out)
{
    extern __shared__ float sm[];
    float* Xs = sm;                        // [64][260]
    u64* WaP = (u64*)(sm + 64 * 260);      // [16][4][17] pairs, W cols kc..
    u64* WbP = WaP + 16 * 68;              // W cols 128+kc..
    u64* WgP = WbP + 16 * 68;              // Wagg cols kc..

    const int t = threadIdx.x;

    // ---- gather phase: 4 threads per row, 32 feats each ----
    {
        int row = t >> 2, q = t & 3, f0 = q * 32;
        size_t i = (size_t)blockIdx.x * 64 + row;
        const float* pd = hdst + i * FEAT + f0;
        const float* ps = hsrc + i * FEAT + f0;
        float4 hd[8], s[8];
#pragma unroll
        for (int j = 0; j < 8; j++) {
            hd[j] = *(const float4*)(pd + 4 * j);
            s[j]  = *(const float4*)(ps + 4 * j);   // self edge
        }
        int eb = n_dst + (int)i * FAN;
#pragma unroll
        for (int e = 0; e < FAN; e++) {
            const float* pe = hsrc + (size_t)srcArr[eb + e] * FEAT + f0;
#pragma unroll
            for (int j = 0; j < 8; j++) {
                float4 u = *(const float4*)(pe + 4 * j);
                s[j].x += u.x; s[j].y += u.y; s[j].z += u.z; s[j].w += u.w;
            }
        }
        float* xr = Xs + row * 260;
#pragma unroll
        for (int j = 0; j < 8; j++) {
            *(float4*)(xr + f0 + 4 * j) = hd[j];
            float4 ag;
            ag.x = (s[j].x - hd[j].x) * 0.125f;
            ag.y = (s[j].y - hd[j].y) * 0.125f;
            ag.z = (s[j].z - hd[j].z) * 0.125f;
            ag.w = (s[j].w - hd[j].w) * 0.125f;
            *(float4*)(xr + 128 + f0 + 4 * j) = ag;
        }
    }
    __syncthreads();

    const int ty = t >> 4, tx = t & 15;
    const int fw = t >> 1, hf = t & 1;
    const int wj = fw >> 5, wh = (fw >> 4) & 1, wtx = fw & 15;
    float* waf = (float*)WaP;
    float* wbf = (float*)WbP;
    float* wgf = (float*)WgP;

    u64 aN[4][4], aA[4][4];
#pragma unroll
    for (int r = 0; r < 4; r++)
#pragma unroll
        for (int j = 0; j < 4; j++) { aN[r][j] = 0ull; aA[r][j] = 0ull; }

    for (int kc = 0; kc < FEAT; kc += 16) {
        float4 v[2], v2[2], v3[2];
#pragma unroll
        for (int q = 0; q < 2; q++) {
            v[q]  = *(const float4*)(W    + (size_t)fw * 256 + kc + hf * 8 + q * 4);
            v2[q] = *(const float4*)(W    + (size_t)fw * 256 + 128 + kc + hf * 8 + q * 4);
            v3[q] = *(const float4*)(Wagg + (size_t)fw * 128 + kc + hf * 8 + q * 4);
        }
        if (kc) __syncthreads();
#pragma unroll
        for (int q = 0; q < 2; q++) {
#pragma unroll
            for (int e = 0; e < 4; e++) {
                int k = hf * 8 + q * 4 + e;
                int fi = 2 * (k * 68 + wj * 17 + wtx) + wh;
                waf[fi] = ((const float*)&v[q])[e];
                wbf[fi] = ((const float*)&v2[q])[e];
                wgf[fi] = ((const float*)&v3[q])[e];
            }
        }
        __syncthreads();

#pragma unroll 4
        for (int k = 0; k < 16; k++) {
            u64 wa[4], wb[4], wg[4];
#pragma unroll
            for (int j = 0; j < 4; j++) {
                wa[j] = WaP[k * 68 + j * 17 + tx];
                wb[j] = WbP[k * 68 + j * 17 + tx];
                wg[j] = WgP[k * 68 + j * 17 + tx];
            }
#pragma unroll
            for (int ri = 0; ri < 4; ri++) {
                const float* xr = Xs + (ty * 4 + ri) * 260;
                float a1 = xr[kc + k];
                float a2 = xr[128 + kc + k];
                u64 p1 = packf2(a1, a1);
                u64 p2 = packf2(a2, a2);
#pragma unroll
                for (int j = 0; j < 4; j++) {
                    aN[ri][j] = fma2(p1, wa[j], aN[ri][j]);
                    aN[ri][j] = fma2(p2, wb[j], aN[ri][j]);
                    aA[ri][j] = fma2(p2, wg[j], aA[ri][j]);
                }
            }
        }
    }

    // ---- epilogue: cols for [j] are (tx+32j, tx+32j+16) ----
    float bv[4][2], bgv[4][2];
#pragma unroll
    for (int j = 0; j < 4; j++) {
        bv[j][0]  = bb[tx + 32 * j];       bv[j][1]  = bb[tx + 32 * j + 16];
        bgv[j][0] = bagg[tx + 32 * j];     bgv[j][1] = bagg[tx + 32 * j + 16];
    }

#pragma unroll
    for (int ri = 0; ri < 4; ri++) {
        size_t irow = (size_t)blockIdx.x * 64 + ty * 4 + ri;
        float h[4][2];
#pragma unroll
        for (int j = 0; j < 4; j++) {
            float n0, n1, a0, a1;
            unpackf2(aN[ri][j], n0, n1);
            unpackf2(aA[ri][j], a0, a1);
            float hn0 = n0 + bv[j][0],  hn1 = n1 + bv[j][1];
            float ha0 = a0 + bgv[j][0], ha1 = a1 + bgv[j][1];
            if (!LAST) { hn0 = leakyf(hn0); hn1 = leakyf(hn1);
                         ha0 = leakyf(ha0); ha1 = leakyf(ha1); }
            h[j][0] = hn0 + ha0; h[j][1] = hn1 + ha1;
        }
        if (!LAST) {
            float ss = 0.f;
#pragma unroll
            for (int j = 0; j < 4; j++) ss += h[j][0] * h[j][0] + h[j][1] * h[j][1];
            ss += __shfl_xor_sync(0xffffffffu, ss, 1);
            ss += __shfl_xor_sync(0xffffffffu, ss, 2);
            ss += __shfl_xor_sync(0xffffffffu, ss, 4);
            ss += __shfl_xor_sync(0xffffffffu, ss, 8);
            float inv = 1.0f / fmaxf(sqrtf(ss), 1e-6f);
#pragma unroll
            for (int j = 0; j < 4; j++) { h[j][0] *= inv; h[j][1] *= inv; }
        }
        float* po = out + irow * FEAT;
#pragma unroll
        for (int j = 0; j < 4; j++) {
            po[tx + 32 * j]      = h[j][0];
            po[tx + 32 * j + 16] = h[j][1];
        }
    }
}

// ---------------- launch -----------------------------------------------------
extern "C" void kernel_launch(void* const* d_in, const int* in_sizes, int n_in,
                              void* d_out, int out_size)
{
    const float* node_emb = (const float*)d_in[0];
    const float* content0 = (const float*)d_in[1];
    const float* Wp       = (const float*)d_in[2];
    const float* bp       = (const float*)d_in[3];
    const float* W0       = (const float*)d_in[4];
    const float* b0       = (const float*)d_in[5];
    const float* Wagg0    = (const float*)d_in[6];
    const float* bagg0    = (const float*)d_in[7];
    const float* W1       = (const float*)d_in[8];
    const float* b1       = (const float*)d_in[9];
    const float* Wagg1    = (const float*)d_in[10];
    const float* bagg1    = (const float*)d_in[11];
    const int*   parent0  = (const int*)d_in[12];
    const int*   src0     = (const int*)d_in[13];
    const int*   src1     = (const int*)d_in[15];
    float* out = (float*)d_out;

    (void)in_sizes; (void)n_in; (void)out_size;

    cudaFuncSetAttribute(k_h0, cudaFuncAttributeMaxDynamicSharedMemorySize, H0_SMEM_BYTES);
    cudaFuncSetAttribute(k_conv<0>, cudaFuncAttributeMaxDynamicSharedMemorySize, CONV_SMEM_BYTES);
    cudaFuncSetAttribute(k_conv<1>, cudaFuncAttributeMaxDynamicSharedMemorySize, CONV_SMEM_BYTES);

    void *p0, *p1;
    cudaGetSymbolAddress(&p0, g_h0);
    cudaGetSymbolAddress(&p1, g_h1);
    float* h0p = (float*)p0;
    float* h1p = (float*)p1;

    k_reset  <<<(S0_N / 16 + 255) / 256, 256>>>();
    k_mark   <<<(9 * S1_N) / 256, 256>>>(src0);
    k_compact<<<S0_N / 256, 256>>>();
    k_h0     <<<S0_N / 128, 256, H0_SMEM_BYTES>>>(content0, Wp, bp, node_emb, parent0);
    k_conv<0><<<S1_N / 64, 256, CONV_SMEM_BYTES>>>(h0p, h0p, src0, S1_N,
                                                   W0, b0, Wagg0, bagg0, h1p);
    k_conv<1><<<S2_N / 64, 256, CONV_SMEM_BYTES>>>(h1p, h0p, src1, S2_N,
                                                   W1, b1, Wagg1, bagg1, out);
}